// round 11
// baseline (speedup 1.0000x reference)
#include <cuda_runtime.h>
#include <cuda_bf16.h>
#include <cstdint>

#define DD    32
#define PREV  64
#define HIDN  128
#define HDIM  64
#define BATCH 8192

// ---------------- HMMA helpers (plain sm_80+ PTX, no 'a' features) ----------
__device__ __forceinline__ void mma16816(float d[4], const uint32_t a[4],
                                         uint32_t b0, uint32_t b1) {
    asm volatile("mma.sync.aligned.m16n8k16.row.col.f32.bf16.bf16.f32 "
        "{%0,%1,%2,%3}, {%4,%5,%6,%7}, {%8,%9}, {%0,%1,%2,%3};"
        : "+f"(d[0]), "+f"(d[1]), "+f"(d[2]), "+f"(d[3])
        : "r"(a[0]), "r"(a[1]), "r"(a[2]), "r"(a[3]), "r"(b0), "r"(b1));
}
// pack two floats as bf16x2 (lo in low half)
__device__ __forceinline__ uint32_t bfpack(float lo, float hi) {
    uint32_t r; asm("cvt.rn.bf16x2.f32 %0, %1, %2;" : "=r"(r) : "f"(hi), "f"(lo));
    return r;
}
__device__ __forceinline__ float bfval(float x) {
    return __bfloat162float(__float2bfloat16(x));
}

// ---------------- batch-independent globals ----------------
// Weight B-fragments in per-lane order: uint2 index = (tile*KC + kc)*32 + lane.
// Element (k,n): lane = (n&7)*4 + ((k&7)>>1), reg = (k>>3)&1, parity = k&1.
__device__ float g_Mf[HIDN * DD];     // fp32 M[h][d] (for c[h] in main)
__device__ float g_beff[HIDN];
__device__ __align__(16) unsigned short g_MBhi[4096]; // GEMM1 B: k=d(32), n=h(128): 16nt x 2kc
__device__ __align__(16) unsigned short g_MBlo[4096];
__device__ __align__(16) unsigned short g_WBhi[4096]; // GEMM2 B: k=h(128), n=d(32): 4dn x 8kc
__device__ __align__(16) unsigned short g_WBlo[4096];

// ---------------- prep: 18 CTAs x 256 threads ----------------
__global__ void __launch_bounds__(256)
prep_kernel(const float* __restrict__ t,   const float* __restrict__ hw1,
            const float* __restrict__ hb1, const float* __restrict__ hw2,
            const float* __restrict__ hb2, const float* __restrict__ bw,
            const float* __restrict__ bb,  const float* __restrict__ w2) {
    __shared__ float hcode[HDIM];
    __shared__ float w1s[2][66];
    __shared__ float b1s[PREV];
    __shared__ float bws[HIDN * 65];

    int tid = threadIdx.x, lane = tid & 31, wrp = tid >> 5;
    int cta = blockIdx.x;

    if (cta == 17) {   // w2 -> GEMM2 B-fragments (k=h, n=d), hi/lo split
        for (int i = tid; i < HIDN * DD; i += 256) {
            int d = i >> 7, h = i & 127;
            float v = w2[i];
            float hv = bfval(v);
            int dn = d >> 3, kc = h >> 4;
            int ln = ((d & 7) << 2) | ((h & 7) >> 1);
            int reg = (h >> 3) & 1, par = h & 1;
            int idx = ((((dn * 8 + kc) * 32 + ln) * 2 + reg) << 1) | par;
            g_WBhi[idx] = __bfloat16_as_ushort(__float2bfloat16(hv));
            g_WBlo[idx] = __bfloat16_as_ushort(__float2bfloat16(v - hv));
        }
        return;
    }

    if (tid < HDIM)
        hcode[tid] = tanhf(t[0] * hw1[tid] + hb1[tid]);
    for (int i = tid; i < HIDN * PREV; i += 256)
        bws[(i >> 6) * 65 + (i & 63)] = bw[i];
    __syncthreads();

    if (cta < 16) {
        int rbase = cta * 128;
#pragma unroll
        for (int rr = wrp; rr < 128; rr += 8) {
            int r = rbase + rr;
            const float* row = hw2 + r * HDIM;
            float acc = hcode[lane] * row[lane] + hcode[lane + 32] * row[lane + 32];
#pragma unroll
            for (int m = 16; m >= 1; m >>= 1)
                acc += __shfl_xor_sync(0xffffffffu, acc, m);
            if (lane == 0) w1s[rr >> 6][rr & 63] = acc + hb2[r];
        }
        __syncthreads();
        int dl = tid & 1, h = tid >> 1;
        int d  = 2 * cta + dl;
        float m = 0.f;
#pragma unroll
        for (int p = 0; p < PREV; p++)
            m += bws[h * 65 + p] * w1s[dl][p];
        g_Mf[h * DD + d] = m;
        // GEMM1 B-fragment (k=d, n=h)
        float hv = bfval(m);
        int nt = h >> 3, kc = d >> 4;
        int ln = ((h & 7) << 2) | ((d & 7) >> 1);
        int reg = (d >> 3) & 1, par = d & 1;
        int idx = ((((nt * 2 + kc) * 32 + ln) * 2 + reg) << 1) | par;
        g_MBhi[idx] = __bfloat16_as_ushort(__float2bfloat16(hv));
        g_MBlo[idx] = __bfloat16_as_ushort(__float2bfloat16(m - hv));
    } else {
#pragma unroll
        for (int rr = wrp; rr < PREV; rr += 8) {
            int r = DD * PREV + rr;
            const float* row = hw2 + r * HDIM;
            float acc = hcode[lane] * row[lane] + hcode[lane + 32] * row[lane + 32];
#pragma unroll
            for (int m = 16; m >= 1; m >>= 1)
                acc += __shfl_xor_sync(0xffffffffu, acc, m);
            if (lane == 0) b1s[rr] = acc + hb2[r];
        }
        __syncthreads();
        if (tid < HIDN) {
            float be = bb[tid];
#pragma unroll
            for (int p = 0; p < PREV; p++)
                be += bws[tid * 65 + p] * b1s[p];
            g_beff[tid] = be;
        }
    }
}

// ---------------- main: 128 CTAs x 128 threads, 64 rows/CTA ----------------
// Warp = 16 rows (one m-tile). GEMM1 (S = X@M^T, K=32): 96 HMMA/warp.
// tanh in registers; GEMM1 D-fragments feed GEMM2 A-fragments directly.
// GEMM2 (dx = A@W2^T, K=128): 96 HMMA/warp. Weights via fragment-ordered LDG.
#define XSTR 34   // even stride -> float2-aligned rows

__global__ void __launch_bounds__(128)
ode_main_kernel(const float* __restrict__ y,
                const float* __restrict__ w2,
                const float* __restrict__ b2,
                float* __restrict__ out) {
    __shared__ __align__(16) float xs[64 * XSTR];  // input tile; reused as output staging
    __shared__ __align__(16) float2 bcs[HIDN];     // (beff, c)
    __shared__ float b2s[DD];

    int tid = threadIdx.x, wid = tid >> 5, lane = tid & 31;
    int rowbase = blockIdx.x * 64;

    for (int i = tid; i < 64 * 32; i += 128) {
        int r = i >> 5, c = i & 31;
        xs[r * XSTR + c] = y[(rowbase + r) * 33 + c];
    }
    if (tid < DD) b2s[tid] = b2[tid];
    {   // c[h] = sum_d M[h,d] * w2[d,h]; thread = h
        float cv = 0.f;
        const float4* mrow = reinterpret_cast<const float4*>(g_Mf + tid * DD);
#pragma unroll
        for (int q = 0; q < 8; q++) {
            float4 mv = mrow[q];
            cv += mv.x * __ldg(&w2[(q * 4 + 0) * HIDN + tid]);
            cv += mv.y * __ldg(&w2[(q * 4 + 1) * HIDN + tid]);
            cv += mv.z * __ldg(&w2[(q * 4 + 2) * HIDN + tid]);
            cv += mv.w * __ldg(&w2[(q * 4 + 3) * HIDN + tid]);
        }
        bcs[tid] = make_float2(g_beff[tid], cv);
    }
    __syncthreads();

    int rr = (wid << 4) + (lane >> 2);   // this lane's row (and rr+8)
    int c0 = (lane & 3) * 2;

    // X A-fragments (bf16 hi/lo), 2 k-chunks of 16
    uint32_t xh[2][4], xl[2][4];
#pragma unroll
    for (int kc = 0; kc < 2; kc++) {
        float2 vv[4];
        vv[0] = *reinterpret_cast<const float2*>(&xs[rr * XSTR + kc * 16 + c0]);
        vv[1] = *reinterpret_cast<const float2*>(&xs[(rr + 8) * XSTR + kc * 16 + c0]);
        vv[2] = *reinterpret_cast<const float2*>(&xs[rr * XSTR + kc * 16 + c0 + 8]);
        vv[3] = *reinterpret_cast<const float2*>(&xs[(rr + 8) * XSTR + kc * 16 + c0 + 8]);
#pragma unroll
        for (int j = 0; j < 4; j++) {
            float hx = bfval(vv[j].x), hy = bfval(vv[j].y);
            xh[kc][j] = bfpack(hx, hy);
            xl[kc][j] = bfpack(vv[j].x - hx, vv[j].y - hy);
        }
    }

    // GEMM1: S = Xhi@Mhi + Xlo@Mhi + Xhi@Mlo
    float acc[16][4];
#pragma unroll
    for (int nt = 0; nt < 16; nt++)
#pragma unroll
        for (int j = 0; j < 4; j++) acc[nt][j] = 0.f;

    const uint2* mbh = reinterpret_cast<const uint2*>(g_MBhi);
    const uint2* mbl = reinterpret_cast<const uint2*>(g_MBlo);
#pragma unroll
    for (int nt = 0; nt < 16; nt++) {
        uint2 h0 = __ldg(mbh + (nt * 2 + 0) * 32 + lane);
        uint2 h1 = __ldg(mbh + (nt * 2 + 1) * 32 + lane);
        uint2 l0 = __ldg(mbl + (nt * 2 + 0) * 32 + lane);
        uint2 l1 = __ldg(mbl + (nt * 2 + 1) * 32 + lane);
        mma16816(acc[nt], xh[0], h0.x, h0.y);
        mma16816(acc[nt], xh[1], h1.x, h1.y);
        mma16816(acc[nt], xl[0], h0.x, h0.y);
        mma16816(acc[nt], xl[1], h1.x, h1.y);
        mma16816(acc[nt], xh[0], l0.x, l0.y);
        mma16816(acc[nt], xh[1], l1.x, l1.y);
    }

    // tanh in-register + GEMM2 (A-fragments == tanh'd D-fragments)
    float acc2[4][4];
#pragma unroll
    for (int dn = 0; dn < 4; dn++)
#pragma unroll
        for (int j = 0; j < 4; j++) acc2[dn][j] = 0.f;
    float dvr = 0.f, dvr8 = 0.f;

    const uint2* wbh = reinterpret_cast<const uint2*>(g_WBhi);
    const uint2* wbl = reinterpret_cast<const uint2*>(g_WBlo);
#pragma unroll
    for (int kc = 0; kc < 8; kc++) {
        uint32_t Ah[4], Al[4];
#pragma unroll
        for (int half = 0; half < 2; half++) {
            int nt = 2 * kc + half;
            float4 bc = *reinterpret_cast<const float4*>(&bcs[nt * 8 + c0]);
            float s0 = acc[nt][0] + bc.x;
            float s1 = acc[nt][1] + bc.z;
            float s2 = acc[nt][2] + bc.x;
            float s3 = acc[nt][3] + bc.z;
            float r0 = __fdividef(2.f, __expf(2.f * s0) + 1.f);
            float r1 = __fdividef(2.f, __expf(2.f * s1) + 1.f);
            float r2 = __fdividef(2.f, __expf(2.f * s2) + 1.f);
            float r3 = __fdividef(2.f, __expf(2.f * s3) + 1.f);
            dvr  += r0 * (2.f - r0) * bc.y + r1 * (2.f - r1) * bc.w;
            dvr8 += r2 * (2.f - r2) * bc.y + r3 * (2.f - r3) * bc.w;
            float a0 = 1.f - r0, a1 = 1.f - r1, a2 = 1.f - r2, a3 = 1.f - r3;
            float h0 = bfval(a0), h1 = bfval(a1), h2 = bfval(a2), h3 = bfval(a3);
            Ah[half * 2 + 0] = bfpack(h0, h1);
            Ah[half * 2 + 1] = bfpack(h2, h3);
            Al[half * 2 + 0] = bfpack(a0 - h0, a1 - h1);
            Al[half * 2 + 1] = bfpack(a2 - h2, a3 - h3);
        }
#pragma unroll
        for (int dn = 0; dn < 4; dn++) {
            uint2 wh = __ldg(wbh + (dn * 8 + kc) * 32 + lane);
            uint2 wl = __ldg(wbl + (dn * 8 + kc) * 32 + lane);
            mma16816(acc2[dn], Ah, wh.x, wh.y);
            mma16816(acc2[dn], Al, wh.x, wh.y);
            mma16816(acc2[dn], Ah, wl.x, wl.y);
        }
    }

    // divergence: reduce over the 4 lanes sharing each row (lane bits 0..1)
    dvr  += __shfl_xor_sync(0xffffffffu, dvr, 1);
    dvr  += __shfl_xor_sync(0xffffffffu, dvr, 2);
    dvr8 += __shfl_xor_sync(0xffffffffu, dvr8, 1);
    dvr8 += __shfl_xor_sync(0xffffffffu, dvr8, 2);

    __syncthreads();   // xs input reads all done; reuse as output staging
#pragma unroll
    for (int dn = 0; dn < 4; dn++) {
        int d0 = dn * 8 + c0;
        xs[rr * XSTR + d0]           = acc2[dn][0] + b2s[d0];
        xs[rr * XSTR + d0 + 1]       = acc2[dn][1] + b2s[d0 + 1];
        xs[(rr + 8) * XSTR + d0]     = acc2[dn][2] + b2s[d0];
        xs[(rr + 8) * XSTR + d0 + 1] = acc2[dn][3] + b2s[d0 + 1];
    }
    if ((lane & 3) == 0) {
        xs[rr * XSTR + 32]       = -dvr;
        xs[(rr + 8) * XSTR + 32] = -dvr8;
    }
    __syncthreads();
    for (int i = tid; i < 64 * 33; i += 128) {
        int r = i / 33, c = i - r * 33;
        out[rowbase * 33 + i] = xs[r * XSTR + c];
    }
}

// ---------------------------------------------------------------------------
// inputs: 0:y 1:t 2:hw1 3:hb1 4:hw2 5:hb2 6:bw 7:bb 8:w2 9:b2
// ---------------------------------------------------------------------------
extern "C" void kernel_launch(void* const* d_in, const int* in_sizes, int n_in,
                              void* d_out, int out_size) {
    const float* y   = (const float*)d_in[0];
    const float* t   = (const float*)d_in[1];
    const float* hw1 = (const float*)d_in[2];
    const float* hb1 = (const float*)d_in[3];
    const float* hw2 = (const float*)d_in[4];
    const float* hb2 = (const float*)d_in[5];
    const float* bw  = (const float*)d_in[6];
    const float* bb  = (const float*)d_in[7];
    const float* w2  = (const float*)d_in[8];
    const float* b2  = (const float*)d_in[9];
    float* out = (float*)d_out;

    prep_kernel<<<18, 256>>>(t, hw1, hb1, hw2, hb2, bw, bb, w2);
    ode_main_kernel<<<BATCH / 64, 128>>>(y, w2, b2, out);
}

// round 12
// speedup vs baseline: 1.3719x; 1.3719x over previous
#include <cuda_runtime.h>
#include <cuda_bf16.h>
#include <cstdint>

#define DD    32
#define PREV  64
#define HIDN  128
#define HDIM  64
#define BATCH 8192

// ---------------- HMMA helpers (plain sm_80+ PTX, no 'a' features) ----------
__device__ __forceinline__ void mma16816(float d[4], const uint32_t a[4],
                                         uint32_t b0, uint32_t b1) {
    asm volatile("mma.sync.aligned.m16n8k16.row.col.f32.bf16.bf16.f32 "
        "{%0,%1,%2,%3}, {%4,%5,%6,%7}, {%8,%9}, {%0,%1,%2,%3};"
        : "+f"(d[0]), "+f"(d[1]), "+f"(d[2]), "+f"(d[3])
        : "r"(a[0]), "r"(a[1]), "r"(a[2]), "r"(a[3]), "r"(b0), "r"(b1));
}
__device__ __forceinline__ uint32_t bfpack(float lo, float hi) {
    uint32_t r; asm("cvt.rn.bf16x2.f32 %0, %1, %2;" : "=r"(r) : "f"(hi), "f"(lo));
    return r;
}
__device__ __forceinline__ float bfval(float x) {
    return __bfloat162float(__float2bfloat16(x));
}

// ---------------- batch-independent globals ----------------
// Weight B-fragments in per-lane order: uint2 index = (tile*KC + kc)*32 + lane.
// Element (k,n): lane = (n&7)*4 + ((k&7)>>1), reg = (k>>3)&1, parity = k&1.
__device__ float g_beff[HIDN];
__device__ float g_cpart[16 * HIDN];  // per-prep-CTA partial of c[h]
__device__ __align__(16) unsigned short g_MBhi[4096]; // GEMM1 B: k=d(32), n=h(128)
__device__ __align__(16) unsigned short g_MBlo[4096];
__device__ __align__(16) unsigned short g_WBhi[4096]; // GEMM2 B: k=h(128), n=d(32)
__device__ __align__(16) unsigned short g_WBlo[4096];

// ---------------- prep: 18 CTAs x 256 threads ----------------
__global__ void __launch_bounds__(256)
prep_kernel(const float* __restrict__ t,   const float* __restrict__ hw1,
            const float* __restrict__ hb1, const float* __restrict__ hw2,
            const float* __restrict__ hb2, const float* __restrict__ bw,
            const float* __restrict__ bb,  const float* __restrict__ w2) {
    __shared__ float hcode[HDIM];
    __shared__ float w1s[2][66];
    __shared__ float b1s[PREV];
    __shared__ float bws[HIDN * 65];

    int tid = threadIdx.x, lane = tid & 31, wrp = tid >> 5;
    int cta = blockIdx.x;

    if (cta == 17) {   // w2 -> GEMM2 B-fragments (k=h, n=d), hi/lo split
        for (int i = tid; i < HIDN * DD; i += 256) {
            int d = i >> 7, h = i & 127;
            float v = w2[i];
            float hv = bfval(v);
            int dn = d >> 3, kc = h >> 4;
            int ln = ((d & 7) << 2) | ((h & 7) >> 1);
            int reg = (h >> 3) & 1, par = h & 1;
            int idx = ((((dn * 8 + kc) * 32 + ln) * 2 + reg) << 1) | par;
            g_WBhi[idx] = __bfloat16_as_ushort(__float2bfloat16(hv));
            g_WBlo[idx] = __bfloat16_as_ushort(__float2bfloat16(v - hv));
        }
        return;
    }

    if (tid < HDIM)
        hcode[tid] = tanhf(t[0] * hw1[tid] + hb1[tid]);
    for (int i = tid; i < HIDN * PREV; i += 256)
        bws[(i >> 6) * 65 + (i & 63)] = bw[i];
    __syncthreads();

    if (cta < 16) {
        int rbase = cta * 128;
#pragma unroll
        for (int rr = wrp; rr < 128; rr += 8) {
            int r = rbase + rr;
            const float* row = hw2 + r * HDIM;
            float acc = hcode[lane] * row[lane] + hcode[lane + 32] * row[lane + 32];
#pragma unroll
            for (int m = 16; m >= 1; m >>= 1)
                acc += __shfl_xor_sync(0xffffffffu, acc, m);
            if (lane == 0) w1s[rr >> 6][rr & 63] = acc + hb2[r];
        }
        __syncthreads();
        int dl = tid & 1, h = tid >> 1;
        int d  = 2 * cta + dl;
        float m = 0.f;
#pragma unroll
        for (int p = 0; p < PREV; p++)
            m += bws[h * 65 + p] * w1s[dl][p];

        // GEMM1 B-fragment (k=d, n=h)
        float hv = bfval(m);
        int nt = h >> 3, kc = d >> 4;
        int ln = ((h & 7) << 2) | ((d & 7) >> 1);
        int reg = (d >> 3) & 1, par = d & 1;
        int idx = ((((nt * 2 + kc) * 32 + ln) * 2 + reg) << 1) | par;
        g_MBhi[idx] = __bfloat16_as_ushort(__float2bfloat16(hv));
        g_MBlo[idx] = __bfloat16_as_ushort(__float2bfloat16(m - hv));

        // partial c[h]: this CTA's two d-values (deterministic pair-sum)
        float part = m * __ldg(&w2[d * HIDN + h]);
        part += __shfl_xor_sync(0xffffffffu, part, 1);
        if (dl == 0) g_cpart[cta * HIDN + h] = part;
    } else {
#pragma unroll
        for (int rr = wrp; rr < PREV; rr += 8) {
            int r = DD * PREV + rr;
            const float* row = hw2 + r * HDIM;
            float acc = hcode[lane] * row[lane] + hcode[lane + 32] * row[lane + 32];
#pragma unroll
            for (int m = 16; m >= 1; m >>= 1)
                acc += __shfl_xor_sync(0xffffffffu, acc, m);
            if (lane == 0) b1s[rr] = acc + hb2[r];
        }
        __syncthreads();
        if (tid < HIDN) {
            float be = bb[tid];
#pragma unroll
            for (int p = 0; p < PREV; p++)
                be += bws[tid * 65 + p] * b1s[p];
            g_beff[tid] = be;
        }
    }
}

// ---------------- main: 512 CTAs x 128 threads, 16 rows/CTA ----------------
// 4 warps split the h-dimension: warp w owns h in [32w, 32w+32).
// GEMM1: 4 nt-tiles/warp (24 HMMA). tanh in registers. GEMM2: 2 k-chunks/warp
// (24 HMMA). dx/dv partials reduced across warps in smem.
#define XSTR 34

__global__ void __launch_bounds__(128)
ode_main_kernel(const float* __restrict__ y,
                const float* __restrict__ b2,
                float* __restrict__ out) {
    __shared__ __align__(16) float xs[16 * XSTR];
    __shared__ __align__(16) float2 bcs[HIDN];     // (beff, c)
    __shared__ float b2s[DD];
    __shared__ __align__(8) float sdx[4][16 * XSTR];
    __shared__ float sdv[4][16];

    int tid = threadIdx.x, wid = tid >> 5, lane = tid & 31;
    int rowbase = blockIdx.x * 16;

    for (int i = tid; i < 16 * 32; i += 128) {
        int r = i >> 5, c = i & 31;
        xs[r * XSTR + c] = y[(rowbase + r) * 33 + c];
    }
    if (tid < HIDN) {
        float cv = 0.f;
#pragma unroll
        for (int b = 0; b < 16; b++) cv += g_cpart[b * HIDN + tid];
        bcs[tid] = make_float2(g_beff[tid], cv);
    }
    if (tid < DD) b2s[tid] = b2[tid];
    __syncthreads();

    int rr = lane >> 2;           // rows rr, rr+8
    int c0 = (lane & 3) * 2;

    // X A-fragments (bf16 hi/lo), 2 k-chunks of 16 (same for all warps)
    uint32_t xh[2][4], xl[2][4];
#pragma unroll
    for (int kc = 0; kc < 2; kc++) {
        float2 vv[4];
        vv[0] = *reinterpret_cast<const float2*>(&xs[rr * XSTR + kc * 16 + c0]);
        vv[1] = *reinterpret_cast<const float2*>(&xs[(rr + 8) * XSTR + kc * 16 + c0]);
        vv[2] = *reinterpret_cast<const float2*>(&xs[rr * XSTR + kc * 16 + c0 + 8]);
        vv[3] = *reinterpret_cast<const float2*>(&xs[(rr + 8) * XSTR + kc * 16 + c0 + 8]);
#pragma unroll
        for (int j = 0; j < 4; j++) {
            float hx = bfval(vv[j].x), hy = bfval(vv[j].y);
            xh[kc][j] = bfpack(hx, hy);
            xl[kc][j] = bfpack(vv[j].x - hx, vv[j].y - hy);
        }
    }

    // GEMM1 for this warp's 4 nt-tiles: S = Xhi@Mhi + Xlo@Mhi + Xhi@Mlo
    float acc[4][4];
#pragma unroll
    for (int l = 0; l < 4; l++)
#pragma unroll
        for (int j = 0; j < 4; j++) acc[l][j] = 0.f;

    const uint2* mbh = reinterpret_cast<const uint2*>(g_MBhi);
    const uint2* mbl = reinterpret_cast<const uint2*>(g_MBlo);
#pragma unroll
    for (int lnt = 0; lnt < 4; lnt++) {
        int nt = wid * 4 + lnt;
        uint2 h0 = __ldg(mbh + (nt * 2 + 0) * 32 + lane);
        uint2 h1 = __ldg(mbh + (nt * 2 + 1) * 32 + lane);
        uint2 l0 = __ldg(mbl + (nt * 2 + 0) * 32 + lane);
        uint2 l1 = __ldg(mbl + (nt * 2 + 1) * 32 + lane);
        mma16816(acc[lnt], xh[0], h0.x, h0.y);
        mma16816(acc[lnt], xh[1], h1.x, h1.y);
        mma16816(acc[lnt], xl[0], h0.x, h0.y);
        mma16816(acc[lnt], xl[1], h1.x, h1.y);
        mma16816(acc[lnt], xh[0], l0.x, l0.y);
        mma16816(acc[lnt], xh[1], l1.x, l1.y);
    }

    // tanh in-register + GEMM2 partial over this warp's 2 k-chunks
    float acc2[4][4];
#pragma unroll
    for (int dn = 0; dn < 4; dn++)
#pragma unroll
        for (int j = 0; j < 4; j++) acc2[dn][j] = 0.f;
    float dvr = 0.f, dvr8 = 0.f;

    const uint2* wbh = reinterpret_cast<const uint2*>(g_WBhi);
    const uint2* wbl = reinterpret_cast<const uint2*>(g_WBlo);
#pragma unroll
    for (int lkc = 0; lkc < 2; lkc++) {
        int kc = wid * 2 + lkc;
        uint32_t Ah[4], Al[4];
#pragma unroll
        for (int half = 0; half < 2; half++) {
            int lnt = 2 * lkc + half;
            int nt  = wid * 4 + lnt;
            float4 bc = *reinterpret_cast<const float4*>(&bcs[nt * 8 + c0]);
            float s0 = acc[lnt][0] + bc.x;
            float s1 = acc[lnt][1] + bc.z;
            float s2 = acc[lnt][2] + bc.x;
            float s3 = acc[lnt][3] + bc.z;
            float r0 = __fdividef(2.f, __expf(2.f * s0) + 1.f);
            float r1 = __fdividef(2.f, __expf(2.f * s1) + 1.f);
            float r2 = __fdividef(2.f, __expf(2.f * s2) + 1.f);
            float r3 = __fdividef(2.f, __expf(2.f * s3) + 1.f);
            dvr  += r0 * (2.f - r0) * bc.y + r1 * (2.f - r1) * bc.w;
            dvr8 += r2 * (2.f - r2) * bc.y + r3 * (2.f - r3) * bc.w;
            float a0 = 1.f - r0, a1 = 1.f - r1, a2 = 1.f - r2, a3 = 1.f - r3;
            float h0 = bfval(a0), h1 = bfval(a1), h2 = bfval(a2), h3 = bfval(a3);
            Ah[half * 2 + 0] = bfpack(h0, h1);
            Ah[half * 2 + 1] = bfpack(h2, h3);
            Al[half * 2 + 0] = bfpack(a0 - h0, a1 - h1);
            Al[half * 2 + 1] = bfpack(a2 - h2, a3 - h3);
        }
#pragma unroll
        for (int dn = 0; dn < 4; dn++) {
            uint2 wh = __ldg(wbh + (dn * 8 + kc) * 32 + lane);
            uint2 wl = __ldg(wbl + (dn * 8 + kc) * 32 + lane);
            mma16816(acc2[dn], Ah, wh.x, wh.y);
            mma16816(acc2[dn], Al, wh.x, wh.y);
            mma16816(acc2[dn], Ah, wl.x, wl.y);
        }
    }

    // dv: reduce over the 4 lanes sharing each row, stash per-warp partials
    dvr  += __shfl_xor_sync(0xffffffffu, dvr, 1);
    dvr  += __shfl_xor_sync(0xffffffffu, dvr, 2);
    dvr8 += __shfl_xor_sync(0xffffffffu, dvr8, 1);
    dvr8 += __shfl_xor_sync(0xffffffffu, dvr8, 2);
    if ((lane & 3) == 0) {
        sdv[wid][rr]     = dvr;
        sdv[wid][rr + 8] = dvr8;
    }
    // dx partials to smem
#pragma unroll
    for (int dn = 0; dn < 4; dn++) {
        int d0 = dn * 8 + c0;
        *reinterpret_cast<float2*>(&sdx[wid][rr * XSTR + d0]) =
            make_float2(acc2[dn][0], acc2[dn][1]);
        *reinterpret_cast<float2*>(&sdx[wid][(rr + 8) * XSTR + d0]) =
            make_float2(acc2[dn][2], acc2[dn][3]);
    }
    __syncthreads();

    // cross-warp reduce + store
    for (int i = tid; i < 16 * 33; i += 128) {
        int r = i / 33, c = i - r * 33;
        float v;
        if (c < 32) {
            v = sdx[0][r * XSTR + c] + sdx[1][r * XSTR + c]
              + sdx[2][r * XSTR + c] + sdx[3][r * XSTR + c] + b2s[c];
        } else {
            v = -(sdv[0][r] + sdv[1][r] + sdv[2][r] + sdv[3][r]);
        }
        out[rowbase * 33 + i] = v;
    }
}

// ---------------------------------------------------------------------------
// inputs: 0:y 1:t 2:hw1 3:hb1 4:hw2 5:hb2 6:bw 7:bb 8:w2 9:b2
// ---------------------------------------------------------------------------
extern "C" void kernel_launch(void* const* d_in, const int* in_sizes, int n_in,
                              void* d_out, int out_size) {
    const float* y   = (const float*)d_in[0];
    const float* t   = (const float*)d_in[1];
    const float* hw1 = (const float*)d_in[2];
    const float* hb1 = (const float*)d_in[3];
    const float* hw2 = (const float*)d_in[4];
    const float* hb2 = (const float*)d_in[5];
    const float* bw  = (const float*)d_in[6];
    const float* bb  = (const float*)d_in[7];
    const float* w2  = (const float*)d_in[8];
    const float* b2  = (const float*)d_in[9];
    float* out = (float*)d_out;

    prep_kernel<<<18, 256>>>(t, hw1, hb1, hw2, hb2, bw, bb, w2);
    ode_main_kernel<<<BATCH / 16, 128>>>(y, b2, out);
}

// round 13
// speedup vs baseline: 1.5350x; 1.1189x over previous
#include <cuda_runtime.h>
#include <cuda_bf16.h>
#include <cstdint>

#define DD    32
#define PREV  64
#define HIDN  128
#define HDIM  64
#define BATCH 8192

// ---------------- HMMA helpers (plain sm_80+ PTX, no 'a' features) ----------
__device__ __forceinline__ void mma16816(float d[4], const uint32_t a[4],
                                         uint32_t b0, uint32_t b1) {
    asm volatile("mma.sync.aligned.m16n8k16.row.col.f32.bf16.bf16.f32 "
        "{%0,%1,%2,%3}, {%4,%5,%6,%7}, {%8,%9}, {%0,%1,%2,%3};"
        : "+f"(d[0]), "+f"(d[1]), "+f"(d[2]), "+f"(d[3])
        : "r"(a[0]), "r"(a[1]), "r"(a[2]), "r"(a[3]), "r"(b0), "r"(b1));
}
__device__ __forceinline__ uint32_t bfpack(float lo, float hi) {
    uint32_t r; asm("cvt.rn.bf16x2.f32 %0, %1, %2;" : "=r"(r) : "f"(hi), "f"(lo));
    return r;
}
__device__ __forceinline__ float bfval(float x) {
    return __bfloat162float(__float2bfloat16(x));
}

// ---------------- batch-independent globals ----------------
// Weight B-fragments in per-lane order: uint2 index = (tile*KC + kc)*32 + lane.
// Element (k,n): lane = (n&7)*4 + ((k&7)>>1), reg = (k>>3)&1, parity = k&1.
__device__ float g_beff[HIDN];
__device__ float g_cpart[16 * HIDN];  // per-prep-CTA partial of c[h]
__device__ __align__(16) unsigned short g_MBhi[4096]; // GEMM1 B: k=d(32), n=h(128)
__device__ __align__(16) unsigned short g_MBlo[4096];
__device__ __align__(16) unsigned short g_WBhi[4096]; // GEMM2 B: k=h(128), n=d(32)
__device__ __align__(16) unsigned short g_WBlo[4096];

// ---------------- prep: 18 CTAs x 256 threads ----------------
__global__ void __launch_bounds__(256)
prep_kernel(const float* __restrict__ t,   const float* __restrict__ hw1,
            const float* __restrict__ hb1, const float* __restrict__ hw2,
            const float* __restrict__ hb2, const float* __restrict__ bw,
            const float* __restrict__ bb,  const float* __restrict__ w2) {
    __shared__ float hcode[HDIM];
    __shared__ float w1s[2][66];
    __shared__ float b1s[PREV];
    __shared__ float bws[HIDN * 65];

    int tid = threadIdx.x, lane = tid & 31, wrp = tid >> 5;
    int cta = blockIdx.x;

    if (cta == 17) {   // w2 -> GEMM2 B-fragments (k=h, n=d), hi/lo split
        for (int i = tid; i < HIDN * DD; i += 256) {
            int d = i >> 7, h = i & 127;
            float v = w2[i];
            float hv = bfval(v);
            int dn = d >> 3, kc = h >> 4;
            int ln = ((d & 7) << 2) | ((h & 7) >> 1);
            int reg = (h >> 3) & 1, par = h & 1;
            int idx = ((((dn * 8 + kc) * 32 + ln) * 2 + reg) << 1) | par;
            g_WBhi[idx] = __bfloat16_as_ushort(__float2bfloat16(hv));
            g_WBlo[idx] = __bfloat16_as_ushort(__float2bfloat16(v - hv));
        }
        return;
    }

    if (tid < HDIM)
        hcode[tid] = tanhf(t[0] * hw1[tid] + hb1[tid]);
    for (int i = tid; i < HIDN * PREV; i += 256)
        bws[(i >> 6) * 65 + (i & 63)] = bw[i];
    __syncthreads();

    if (cta < 16) {
        int rbase = cta * 128;
#pragma unroll
        for (int rr = wrp; rr < 128; rr += 8) {
            int r = rbase + rr;
            const float* row = hw2 + r * HDIM;
            float acc = hcode[lane] * row[lane] + hcode[lane + 32] * row[lane + 32];
#pragma unroll
            for (int m = 16; m >= 1; m >>= 1)
                acc += __shfl_xor_sync(0xffffffffu, acc, m);
            if (lane == 0) w1s[rr >> 6][rr & 63] = acc + hb2[r];
        }
        __syncthreads();
        int dl = tid & 1, h = tid >> 1;
        int d  = 2 * cta + dl;
        float m = 0.f;
#pragma unroll
        for (int p = 0; p < PREV; p++)
            m += bws[h * 65 + p] * w1s[dl][p];

        // GEMM1 B-fragment (k=d, n=h)
        float hv = bfval(m);
        int nt = h >> 3, kc = d >> 4;
        int ln = ((h & 7) << 2) | ((d & 7) >> 1);
        int reg = (d >> 3) & 1, par = d & 1;
        int idx = ((((nt * 2 + kc) * 32 + ln) * 2 + reg) << 1) | par;
        g_MBhi[idx] = __bfloat16_as_ushort(__float2bfloat16(hv));
        g_MBlo[idx] = __bfloat16_as_ushort(__float2bfloat16(m - hv));

        // partial c[h]: this CTA's two d-values (deterministic pair-sum)
        float part = m * __ldg(&w2[d * HIDN + h]);
        part += __shfl_xor_sync(0xffffffffu, part, 1);
        if (dl == 0) g_cpart[cta * HIDN + h] = part;
    } else {
#pragma unroll
        for (int rr = wrp; rr < PREV; rr += 8) {
            int r = DD * PREV + rr;
            const float* row = hw2 + r * HDIM;
            float acc = hcode[lane] * row[lane] + hcode[lane + 32] * row[lane + 32];
#pragma unroll
            for (int m = 16; m >= 1; m >>= 1)
                acc += __shfl_xor_sync(0xffffffffu, acc, m);
            if (lane == 0) b1s[rr] = acc + hb2[r];
        }
        __syncthreads();
        if (tid < HIDN) {
            float be = bb[tid];
#pragma unroll
            for (int p = 0; p < PREV; p++)
                be += bws[tid * 65 + p] * b1s[p];
            g_beff[tid] = be;
        }
    }
}

// ---------------- main: 512 CTAs x 256 threads, 16 rows/CTA ----------------
// 8 warps split the h-dimension: warp w owns h in [16w, 16w+16).
// GEMM1: 2 nt-tiles/warp (12 HMMA). tanh in registers. GEMM2: 1 k-chunk/warp
// (12 HMMA). dx/dv partials reduced across 8 warps in smem.
#define XSTR 34

__global__ void __launch_bounds__(256)
ode_main_kernel(const float* __restrict__ y,
                const float* __restrict__ b2,
                float* __restrict__ out) {
    __shared__ __align__(16) float xs[16 * XSTR];
    __shared__ __align__(16) float2 bcs[HIDN];     // (beff, c)
    __shared__ float b2s[DD];
    __shared__ __align__(8) float sdx[8][16 * XSTR];
    __shared__ float sdv[8][16];

    int tid = threadIdx.x, wid = tid >> 5, lane = tid & 31;
    int rowbase = blockIdx.x * 16;

    for (int i = tid; i < 16 * 32; i += 256) {
        int r = i >> 5, c = i & 31;
        xs[r * XSTR + c] = y[(rowbase + r) * 33 + c];
    }
    if (tid < HIDN) {
        float cv = 0.f;
#pragma unroll
        for (int b = 0; b < 16; b++) cv += g_cpart[b * HIDN + tid];
        bcs[tid] = make_float2(g_beff[tid], cv);
    }
    if (tid < DD) b2s[tid] = b2[tid];
    __syncthreads();

    int rr = lane >> 2;           // rows rr, rr+8
    int c0 = (lane & 3) * 2;

    // X A-fragments (bf16 hi/lo), 2 k-chunks of 16 (same for all warps)
    uint32_t xh[2][4], xl[2][4];
#pragma unroll
    for (int kc = 0; kc < 2; kc++) {
        float2 vv[4];
        vv[0] = *reinterpret_cast<const float2*>(&xs[rr * XSTR + kc * 16 + c0]);
        vv[1] = *reinterpret_cast<const float2*>(&xs[(rr + 8) * XSTR + kc * 16 + c0]);
        vv[2] = *reinterpret_cast<const float2*>(&xs[rr * XSTR + kc * 16 + c0 + 8]);
        vv[3] = *reinterpret_cast<const float2*>(&xs[(rr + 8) * XSTR + kc * 16 + c0 + 8]);
#pragma unroll
        for (int j = 0; j < 4; j++) {
            float hx = bfval(vv[j].x), hy = bfval(vv[j].y);
            xh[kc][j] = bfpack(hx, hy);
            xl[kc][j] = bfpack(vv[j].x - hx, vv[j].y - hy);
        }
    }

    // GEMM1 for this warp's 2 nt-tiles: S = Xhi@Mhi + Xlo@Mhi + Xhi@Mlo
    float acc[2][4];
#pragma unroll
    for (int l = 0; l < 2; l++)
#pragma unroll
        for (int j = 0; j < 4; j++) acc[l][j] = 0.f;

    const uint2* mbh = reinterpret_cast<const uint2*>(g_MBhi);
    const uint2* mbl = reinterpret_cast<const uint2*>(g_MBlo);
#pragma unroll
    for (int lnt = 0; lnt < 2; lnt++) {
        int nt = wid * 2 + lnt;
        uint2 h0 = __ldg(mbh + (nt * 2 + 0) * 32 + lane);
        uint2 h1 = __ldg(mbh + (nt * 2 + 1) * 32 + lane);
        uint2 l0 = __ldg(mbl + (nt * 2 + 0) * 32 + lane);
        uint2 l1 = __ldg(mbl + (nt * 2 + 1) * 32 + lane);
        mma16816(acc[lnt], xh[0], h0.x, h0.y);
        mma16816(acc[lnt], xh[1], h1.x, h1.y);
        mma16816(acc[lnt], xl[0], h0.x, h0.y);
        mma16816(acc[lnt], xl[1], h1.x, h1.y);
        mma16816(acc[lnt], xh[0], l0.x, l0.y);
        mma16816(acc[lnt], xh[1], l1.x, l1.y);
    }

    // tanh in-register + GEMM2 partial over this warp's k-chunk (kc = wid)
    float acc2[4][4];
#pragma unroll
    for (int dn = 0; dn < 4; dn++)
#pragma unroll
        for (int j = 0; j < 4; j++) acc2[dn][j] = 0.f;
    float dvr = 0.f, dvr8 = 0.f;

    uint32_t Ah[4], Al[4];
#pragma unroll
    for (int half = 0; half < 2; half++) {
        int nt = wid * 2 + half;
        float4 bc = *reinterpret_cast<const float4*>(&bcs[nt * 8 + c0]);
        float s0 = acc[half][0] + bc.x;
        float s1 = acc[half][1] + bc.z;
        float s2 = acc[half][2] + bc.x;
        float s3 = acc[half][3] + bc.z;
        float r0 = __fdividef(2.f, __expf(2.f * s0) + 1.f);
        float r1 = __fdividef(2.f, __expf(2.f * s1) + 1.f);
        float r2 = __fdividef(2.f, __expf(2.f * s2) + 1.f);
        float r3 = __fdividef(2.f, __expf(2.f * s3) + 1.f);
        dvr  += r0 * (2.f - r0) * bc.y + r1 * (2.f - r1) * bc.w;
        dvr8 += r2 * (2.f - r2) * bc.y + r3 * (2.f - r3) * bc.w;
        float a0 = 1.f - r0, a1 = 1.f - r1, a2 = 1.f - r2, a3 = 1.f - r3;
        float h0 = bfval(a0), h1 = bfval(a1), h2 = bfval(a2), h3 = bfval(a3);
        Ah[half * 2 + 0] = bfpack(h0, h1);
        Ah[half * 2 + 1] = bfpack(h2, h3);
        Al[half * 2 + 0] = bfpack(a0 - h0, a1 - h1);
        Al[half * 2 + 1] = bfpack(a2 - h2, a3 - h3);
    }
    const uint2* wbh = reinterpret_cast<const uint2*>(g_WBhi);
    const uint2* wbl = reinterpret_cast<const uint2*>(g_WBlo);
#pragma unroll
    for (int dn = 0; dn < 4; dn++) {
        uint2 wh = __ldg(wbh + (dn * 8 + wid) * 32 + lane);
        uint2 wl = __ldg(wbl + (dn * 8 + wid) * 32 + lane);
        mma16816(acc2[dn], Ah, wh.x, wh.y);
        mma16816(acc2[dn], Al, wh.x, wh.y);
        mma16816(acc2[dn], Ah, wl.x, wl.y);
    }

    // dv: reduce over the 4 lanes sharing each row, stash per-warp partials
    dvr  += __shfl_xor_sync(0xffffffffu, dvr, 1);
    dvr  += __shfl_xor_sync(0xffffffffu, dvr, 2);
    dvr8 += __shfl_xor_sync(0xffffffffu, dvr8, 1);
    dvr8 += __shfl_xor_sync(0xffffffffu, dvr8, 2);
    if ((lane & 3) == 0) {
        sdv[wid][rr]     = dvr;
        sdv[wid][rr + 8] = dvr8;
    }
    // dx partials to smem
#pragma unroll
    for (int dn = 0; dn < 4; dn++) {
        int d0 = dn * 8 + c0;
        *reinterpret_cast<float2*>(&sdx[wid][rr * XSTR + d0]) =
            make_float2(acc2[dn][0], acc2[dn][1]);
        *reinterpret_cast<float2*>(&sdx[wid][(rr + 8) * XSTR + d0]) =
            make_float2(acc2[dn][2], acc2[dn][3]);
    }
    __syncthreads();

    // cross-warp reduce + store
    for (int i = tid; i < 16 * 33; i += 256) {
        int r = i / 33, c = i - r * 33;
        float v;
        if (c < 32) {
            v = ((sdx[0][r * XSTR + c] + sdx[1][r * XSTR + c])
               + (sdx[2][r * XSTR + c] + sdx[3][r * XSTR + c]))
              + ((sdx[4][r * XSTR + c] + sdx[5][r * XSTR + c])
               + (sdx[6][r * XSTR + c] + sdx[7][r * XSTR + c])) + b2s[c];
        } else {
            v = -(((sdv[0][r] + sdv[1][r]) + (sdv[2][r] + sdv[3][r]))
                + ((sdv[4][r] + sdv[5][r]) + (sdv[6][r] + sdv[7][r])));
        }
        out[rowbase * 33 + i] = v;
    }
}

// ---------------------------------------------------------------------------
// inputs: 0:y 1:t 2:hw1 3:hb1 4:hw2 5:hb2 6:bw 7:bb 8:w2 9:b2
// ---------------------------------------------------------------------------
extern "C" void kernel_launch(void* const* d_in, const int* in_sizes, int n_in,
                              void* d_out, int out_size) {
    const float* y   = (const float*)d_in[0];
    const float* t   = (const float*)d_in[1];
    const float* hw1 = (const float*)d_in[2];
    const float* hb1 = (const float*)d_in[3];
    const float* hw2 = (const float*)d_in[4];
    const float* hb2 = (const float*)d_in[5];
    const float* bw  = (const float*)d_in[6];
    const float* bb  = (const float*)d_in[7];
    const float* w2  = (const float*)d_in[8];
    const float* b2  = (const float*)d_in[9];
    float* out = (float*)d_out;

    prep_kernel<<<18, 256>>>(t, hw1, hb1, hw2, hb2, bw, bb, w2);
    ode_main_kernel<<<BATCH / 16, 256>>>(y, b2, out);
}